// round 14
// baseline (speedup 1.0000x reference)
#include <cuda_runtime.h>
#include <cuda_fp16.h>
#include <math.h>
#include <stdint.h>

#define NT 4096   // tokens (B*S)
#define HD 1024   // hidden
#define ID 4096   // intermediate
#define NE 8      // experts

#define BK 64
#define SA 72                 // SMEM row stride (fp16 elems): 64 data + 8 pad (144B)
#define ROWB 144

#define N1TILES 4096          // FFN1: (32 m) x (16 n) x (8 e), expert-major
#define N2TILES 4096          // FFN2: (64 m) x (8 n) x (8 e), expert-major
#define NTILES (N1TILES + N2TILES)

// ---------------- scratch (static device globals; no allocs) ----------------
__device__ int   g_cnt[NE];
__device__ int   g_work;
__device__ int   g_exit;
__device__ volatile int g_f1done[NE];
__device__ int   g_w2done;
__device__ volatile int g_w2rdy;
__device__ int   g_tok[NE * NT];
__device__ float g_wgt[NE * NT];
__device__ __half g_xh[(size_t)NT * HD];
__device__ __half g_w1[(size_t)NE * ID * HD];
__device__ __half g_w2[(size_t)NE * HD * ID];
__device__ __half g_act[(size_t)NE * NT * ID];

// ---------------- helpers ----------------
__device__ __forceinline__ void cp16(uint32_t dst, const void* src) {
    asm volatile("cp.async.cg.shared.global [%0], [%1], 16;" :: "r"(dst), "l"(src));
}
#define CP_COMMIT() asm volatile("cp.async.commit_group;" ::: "memory")
template <int N>
__device__ __forceinline__ void cp_wait() {
    asm volatile("cp.async.wait_group %0;" :: "n"(N) : "memory");
}
__device__ __forceinline__ uint32_t smem_to_u32(const void* p) {
    uint32_t a;
    asm("{ .reg .u64 t; cvta.to.shared.u64 t, %1; cvt.u32.u64 %0, t; }" : "=r"(a) : "l"(p));
    return a;
}
__device__ __forceinline__ void ldsm_x4(uint32_t* r, uint32_t addr) {
    asm volatile("ldmatrix.sync.aligned.m8n8.x4.shared.b16 {%0,%1,%2,%3}, [%4];"
                 : "=r"(r[0]), "=r"(r[1]), "=r"(r[2]), "=r"(r[3]) : "r"(addr));
}
__device__ __forceinline__ void mma16816(float* d, const uint32_t* a, const uint32_t* b) {
    asm volatile(
        "mma.sync.aligned.m16n8k16.row.col.f32.f16.f16.f32 "
        "{%0,%1,%2,%3}, {%4,%5,%6,%7}, {%8,%9}, {%0,%1,%2,%3};"
        : "+f"(d[0]), "+f"(d[1]), "+f"(d[2]), "+f"(d[3])
        : "r"(a[0]), "r"(a[1]), "r"(a[2]), "r"(a[3]), "r"(b[0]), "r"(b[1]));
}
__device__ __forceinline__ float gelu_exact(float v) {
    return 0.5f * v * (1.f + erff(v * 0.70710678118654752f));
}

// ---------------- zero the output (for atomic combine) ----------------
__global__ void zero_kernel(float4* __restrict__ p, int n4) {
    int i = blockIdx.x * blockDim.x + threadIdx.x;
    int stride = gridDim.x * blockDim.x;
    for (; i < n4; i += stride) p[i] = make_float4(0.f, 0.f, 0.f, 0.f);
}

// ---------------- router + x->fp16 conversion fused: one warp per token ----------------
__global__ void router_kernel(const float* __restrict__ x,
                              const float* __restrict__ Wg) {
    int warp = (blockIdx.x * blockDim.x + threadIdx.x) >> 5;
    int lane = threadIdx.x & 31;
    if (warp >= NT) return;
    const float4* xr = (const float4*)(x + (size_t)warp * HD);

    float4 xv[8];
#pragma unroll
    for (int j = 0; j < 8; j++) xv[j] = xr[lane + j * 32];

    __half2* xo = (__half2*)(g_xh + (size_t)warp * HD);
#pragma unroll
    for (int j = 0; j < 8; j++) {
        int c2 = (lane + j * 32) * 2;
        xo[c2 + 0] = __half2(__float2half_rn(xv[j].x), __float2half_rn(xv[j].y));
        xo[c2 + 1] = __half2(__float2half_rn(xv[j].z), __float2half_rn(xv[j].w));
    }

    float logit[NE];
#pragma unroll
    for (int e = 0; e < NE; e++) {
        const float4* w = (const float4*)(Wg + e * HD);
        float s = 0.f;
#pragma unroll
        for (int j = 0; j < 8; j++) {
            float4 wv = w[lane + j * 32];
            s += xv[j].x * wv.x + xv[j].y * wv.y + xv[j].z * wv.z + xv[j].w * wv.w;
        }
#pragma unroll
        for (int o = 16; o; o >>= 1) s += __shfl_xor_sync(0xffffffffu, s, o);
        logit[e] = s;
    }

    if (lane == 0) {
        int e0 = 0; float l0 = logit[0];
#pragma unroll
        for (int e = 1; e < NE; e++) if (logit[e] > l0) { l0 = logit[e]; e0 = e; }
        int e1 = -1; float l1 = -3.0e38f;
#pragma unroll
        for (int e = 0; e < NE; e++)
            if (e != e0 && logit[e] > l1) { l1 = logit[e]; e1 = e; }
        float w0 = 1.f / (1.f + expf(l1 - l0));
        float w1 = 1.f - w0;

        int s0 = atomicAdd(&g_cnt[e0], 1);
        g_tok[e0 * NT + s0] = warp;
        g_wgt[e0 * NT + s0] = w0;

        int s1 = atomicAdd(&g_cnt[e1], 1);
        g_tok[e1 * NT + s1] = warp;
        g_wgt[e1 * NT + s1] = w1;
    }
}

// ---------------- f32 -> fp16 conversion (W1), 16B stores ----------------
__global__ void wconv_kernel(const float4* __restrict__ src,
                             uint4* __restrict__ h, int n8) {
    int i = blockIdx.x * blockDim.x + threadIdx.x;
    int stride = gridDim.x * blockDim.x;
    for (; i < n8; i += stride) {
        float4 v0 = src[2 * i + 0];
        float4 v1 = src[2 * i + 1];
        __half2 a(__float2half_rn(v0.x), __float2half_rn(v0.y));
        __half2 b(__float2half_rn(v0.z), __float2half_rn(v0.w));
        __half2 c(__float2half_rn(v1.x), __float2half_rn(v1.y));
        __half2 d(__float2half_rn(v1.z), __float2half_rn(v1.w));
        uint4 o;
        o.x = *(uint32_t*)&a; o.y = *(uint32_t*)&b;
        o.z = *(uint32_t*)&c; o.w = *(uint32_t*)&d;
        h[i] = o;
    }
}

// ---------------- W2 conversion; last CTA raises g_w2rdy ----------------
#define W2_CTAS 4096
__global__ void wconv2_kernel(const float4* __restrict__ src, uint4* __restrict__ h) {
    const int n8 = NE * ID * HD / 8;
    int i = blockIdx.x * blockDim.x + threadIdx.x;
    int stride = W2_CTAS * blockDim.x;
    for (; i < n8; i += stride) {
        float4 v0 = src[2 * i + 0];
        float4 v1 = src[2 * i + 1];
        __half2 a(__float2half_rn(v0.x), __float2half_rn(v0.y));
        __half2 b(__float2half_rn(v0.z), __float2half_rn(v0.w));
        __half2 c(__float2half_rn(v1.x), __float2half_rn(v1.y));
        __half2 d(__float2half_rn(v1.z), __float2half_rn(v1.w));
        uint4 o;
        o.x = *(uint32_t*)&a; o.y = *(uint32_t*)&b;
        o.z = *(uint32_t*)&c; o.w = *(uint32_t*)&d;
        h[i] = o;
    }
    __threadfence();
    __syncthreads();
    if (threadIdx.x == 0) {
        if (atomicAdd(&g_w2done, 1) == W2_CTAS - 1) {
            __threadfence();
            g_w2rdy = 1;
        }
    }
}

// ---------------- GEMM tile body (shared by both roles) ----------------
template <int KDIM, int BROWS, bool GELU_OUT, bool GATHER_A, int TBM, int TBN, int WTM, int WTN>
__device__ __forceinline__ void ffn_body(int m0, int n0, int e, int cnt,
                                         const __half* __restrict__ A,
                                         const __half* __restrict__ B,
                                         const float* __restrict__ bias,
                                         float* __restrict__ out, char* smem) {
    constexpr int STAGE = (TBM + TBN) * ROWB;
    constexpr int MT = WTM / 16;
    constexpr int PT = WTN / 16;
    constexpr int NS = KDIM / BK;
    constexpr int AJ = TBM * 8 / 256;
    constexpr int BJ = TBN * 8 / 256;

    uint32_t sb = smem_to_u32(smem);
    int tid = threadIdx.x;
    int wid = tid >> 5;
    int lane = tid & 31;
    int g = lane >> 2, t = lane & 3;
    int wm = (wid >> 2) * WTM;
    int wn = (wid & 3) * WTN;

    int la = lane & 7;
    int ar = la + 8 * ((lane >> 3) & 1);
    int ak = 8 * (lane >> 4);
    int br = la + 8 * ((lane >> 4) & 1);
    int bk = 8 * ((lane >> 3) & 1);

    const __half* aptr[AJ]; uint32_t aoff[AJ];
    const __half* bptr[BJ]; uint32_t boff[BJ];
#pragma unroll
    for (int j = 0; j < AJ; j++) {
        int c = tid + j * 256;
        int r = c >> 3, ch = c & 7;
        aoff[j] = (uint32_t)(r * ROWB + ch * 16);
        int m = m0 + r;
        if (GATHER_A) {
            int mm = (m < cnt) ? m : (cnt - 1);
            aptr[j] = A + (size_t)g_tok[e * NT + mm] * KDIM + ch * 8;
        } else {
            aptr[j] = A + (size_t)(e * NT + m) * KDIM + ch * 8;
        }
    }
#pragma unroll
    for (int j = 0; j < BJ; j++) {
        int c = tid + j * 256;
        int r = c >> 3, ch = c & 7;
        boff[j] = (uint32_t)(TBM * ROWB + r * ROWB + ch * 16);
        bptr[j] = B + (size_t)(e * BROWS + n0 + r) * KDIM + ch * 8;
    }

    auto load_stage = [&](uint32_t base, int k0) {
#pragma unroll
        for (int j = 0; j < AJ; j++) cp16(base + aoff[j], aptr[j] + k0);
#pragma unroll
        for (int j = 0; j < BJ; j++) cp16(base + boff[j], bptr[j] + k0);
    };

    load_stage(sb, 0);
    CP_COMMIT();

    float acc[MT][WTN / 8][4] = {};

    for (int i = 0; i < NS; i++) {
        if (i + 1 < NS) {
            load_stage(sb + (uint32_t)(((i + 1) & 1) * STAGE), (i + 1) * BK);
            CP_COMMIT();
        }
        if (i + 1 < NS) cp_wait<1>(); else cp_wait<0>();
        __syncthreads();

        uint32_t sAu = sb + (uint32_t)((i & 1) * STAGE);
        uint32_t sBu = sAu + TBM * ROWB;

#pragma unroll
        for (int kk = 0; kk < BK; kk += 16) {
            uint32_t AH[MT][4], BB[PT][4];
#pragma unroll
            for (int mt = 0; mt < MT; mt++)
                ldsm_x4(AH[mt], sAu + (uint32_t)(((wm + mt * 16 + ar) * SA + kk + ak) * 2));
#pragma unroll
            for (int p = 0; p < PT; p++)
                ldsm_x4(BB[p], sBu + (uint32_t)(((wn + p * 16 + br) * SA + kk + bk) * 2));
#pragma unroll
            for (int p = 0; p < PT; p++) {
#pragma unroll
                for (int mt = 0; mt < MT; mt++) {
                    mma16816(acc[mt][2 * p + 0], AH[mt], &BB[p][0]);
                    mma16816(acc[mt][2 * p + 1], AH[mt], &BB[p][2]);
                }
            }
        }
        __syncthreads();
    }

#pragma unroll
    for (int mt = 0; mt < MT; mt++) {
        int r0 = m0 + wm + mt * 16 + g;
        int r1 = r0 + 8;
        int tok0 = 0, tok1 = 0;
        float wg0 = 0.f, wg1 = 0.f;
        bool ok0 = false, ok1 = false;
        if (!GELU_OUT) {
            ok0 = (r0 < cnt);
            ok1 = (r1 < cnt);
            if (ok0) { tok0 = g_tok[e * NT + r0]; wg0 = g_wgt[e * NT + r0]; }
            if (ok1) { tok1 = g_tok[e * NT + r1]; wg1 = g_wgt[e * NT + r1]; }
        }
#pragma unroll
        for (int nt = 0; nt < WTN / 8; nt++) {
            int col = n0 + wn + nt * 8 + 2 * t;
            float2 bb = *(const float2*)&bias[(size_t)e * BROWS + col];
            float* c = acc[mt][nt];
            float v00 = c[0] + bb.x, v01 = c[1] + bb.y;
            float v10 = c[2] + bb.x, v11 = c[3] + bb.y;
            if (GELU_OUT) {
                float g00 = gelu_exact(v00), g01 = gelu_exact(v01);
                float g10 = gelu_exact(v10), g11 = gelu_exact(v11);
                size_t o0 = ((size_t)e * NT + r0) * ID + col;
                size_t o1 = ((size_t)e * NT + r1) * ID + col;
                *(__half2*)&g_act[o0] = __half2(__float2half_rn(g00), __float2half_rn(g01));
                *(__half2*)&g_act[o1] = __half2(__float2half_rn(g10), __float2half_rn(g11));
            } else {
                if (ok0) {
                    atomicAdd(&out[(size_t)tok0 * HD + col + 0], wg0 * v00);
                    atomicAdd(&out[(size_t)tok0 * HD + col + 1], wg0 * v01);
                }
                if (ok1) {
                    atomicAdd(&out[(size_t)tok1 * HD + col + 0], wg1 * v10);
                    atomicAdd(&out[(size_t)tok1 * HD + col + 1], wg1 * v11);
                }
            }
        }
    }
}

// ---------------- persistent fused FFN1+FFN2 kernel (device work queue) ----------------
// Tiles 0..N1TILES-1: FFN1, expert-major (e = t>>9, m = (t&31)*128, n = ((t>>5)&15)*256)
// Tiles N1TILES..  : FFN2, expert-major (e = t>>9, m = (t&63)*64,  n = ((t>>6)&7)*128)
// Grid = #SMs, 1 CTA/SM by smem => all CTAs resident => spin-wait is deadlock-free:
// every claimed FFN1 tile is executed by a resident, never-spinning CTA, and all
// FFN1 tiles are claimed before any FFN2 tile (single monotone counter).
__global__ void __launch_bounds__(256)
fused_moe_kernel(const __half* __restrict__ xh, const __half* __restrict__ w1,
                 const float* __restrict__ b1,
                 const __half* __restrict__ w2, const float* __restrict__ b2,
                 float* __restrict__ out) {
    extern __shared__ char smem[];
    __shared__ int sTile;
    int tid = threadIdx.x;

    for (;;) {
        if (tid == 0) sTile = atomicAdd(&g_work, 1);
        __syncthreads();
        int tile = sTile;
        __syncthreads();       // sTile consumed before next overwrite; smem tile reuse safe
        if (tile >= NTILES) break;

        if (tile < N1TILES) {
            int e = tile >> 9;
            int cnt = g_cnt[e];
            int m0 = (tile & 31) * 128;
            int n0 = ((tile >> 5) & 15) * 256;
            if (m0 < cnt) {
                ffn_body<HD, ID, true, true, 128, 256, 64, 64>(
                    m0, n0, e, cnt, xh, w1, b1, nullptr, smem);
            }
            __threadfence();
            __syncthreads();
            if (tid == 0) atomicAdd((int*)&g_f1done[e], 1);
        } else {
            int b = tile - N1TILES;
            int e = b >> 9;
            int cnt = g_cnt[e];
            int m0 = (b & 63) * 64;
            int n0 = ((b >> 6) & 7) * 128;
            if (m0 < cnt) {
                if (tid == 0) {
                    while (g_w2rdy == 0) {}
                    while (g_f1done[e] < 512) {}
                    __threadfence();
                }
                __syncthreads();
                ffn_body<ID, HD, false, false, 64, 128, 32, 32>(
                    m0, n0, e, cnt, g_act, w2, b2, out, smem);
            }
            __syncthreads();
        }
    }

    // last CTA to exit resets all device state for the next (replayed) call
    if (tid == 0) {
        __threadfence();
        if (atomicAdd(&g_exit, 1) == (int)gridDim.x - 1) {
#pragma unroll
            for (int i = 0; i < NE; i++) {
                g_cnt[i] = 0;
                *(int*)&g_f1done[i] = 0;
            }
            g_work = 0;
            g_exit = 0;
            g_w2done = 0;
            g_w2rdy = 0;
            __threadfence();
        }
    }
}

#define FUSED_SMEM (2 * (128 + 256) * ROWB)

extern "C" void kernel_launch(void* const* d_in, const int* in_sizes, int n_in,
                              void* d_out, int out_size) {
    const float* x  = (const float*)d_in[0];
    const float* Wg = (const float*)d_in[1];
    const float* W1 = (const float*)d_in[2];
    const float* b1 = (const float*)d_in[3];
    const float* W2 = (const float*)d_in[4];
    const float* b2 = (const float*)d_in[5];
    float* out = (float*)d_out;

    static int init_done = 0;
    static int n_sms = 0;
    static cudaStream_t sW;
    static cudaEvent_t evFork, evW1, evSide;
    if (!init_done) {
        cudaFuncSetAttribute((const void*)fused_moe_kernel,
                             cudaFuncAttributeMaxDynamicSharedMemorySize, FUSED_SMEM);
        cudaDeviceGetAttribute(&n_sms, cudaDevAttrMultiProcessorCount, 0);
        cudaStreamCreateWithFlags(&sW, cudaStreamNonBlocking);
        cudaEventCreateWithFlags(&evFork, cudaEventDisableTiming);
        cudaEventCreateWithFlags(&evW1, cudaEventDisableTiming);
        cudaEventCreateWithFlags(&evSide, cudaEventDisableTiming);
        init_done = 1;
    }

    uint4 *w1, *w2;
    cudaGetSymbolAddress((void**)&w1, g_w1);
    cudaGetSymbolAddress((void**)&w2, g_w2);
    const __half* xhp;
    cudaGetSymbolAddress((void**)&xhp, g_xh);

    const int n8w = NE * ID * HD / 8;

    // fork: side stream converts W1 (gates fused launch), zeroes out,
    // converts W2 (raises device flag g_w2rdy consumed by FFN2 tiles).
    cudaEventRecord(evFork, 0);
    cudaStreamWaitEvent(sW, evFork, 0);
    wconv_kernel<<<4096, 256, 0, sW>>>((const float4*)W1, w1, n8w);
    cudaEventRecord(evW1, sW);
    zero_kernel<<<1024, 256, 0, sW>>>((float4*)out, NT * HD / 4);
    wconv2_kernel<<<W2_CTAS, 256, 0, sW>>>((const float4*)W2, w2);
    cudaEventRecord(evSide, sW);

    router_kernel<<<NT / 8, 256>>>(x, Wg);

    cudaStreamWaitEvent(0, evW1, 0);   // fused kernel needs w1 at start
    fused_moe_kernel<<<n_sms, 256, FUSED_SMEM>>>(
        xhp, (const __half*)w1, b1, (const __half*)w2, b2, out);

    cudaStreamWaitEvent(0, evSide, 0); // join side stream for graph capture
}

// round 15
// speedup vs baseline: 1.2013x; 1.2013x over previous
#include <cuda_runtime.h>
#include <cuda_fp16.h>
#include <math.h>
#include <stdint.h>

#define NT 4096   // tokens (B*S)
#define HD 1024   // hidden
#define ID 4096   // intermediate
#define NE 8      // experts

#define BK 64
#define SA 72                 // SMEM row stride (fp16 elems): 64 data + 8 pad (144B)
#define ROWB 144

// ---------------- scratch (static device globals; no allocs) ----------------
__device__ int   g_cnt[NE];
__device__ int   g_work1;
__device__ int   g_work2;
__device__ int   g_exit;
__device__ int   g_tok[NE * NT];
__device__ float g_wgt[NE * NT];
__device__ __half g_xh[(size_t)NT * HD];
__device__ __half g_w1[(size_t)NE * ID * HD];
__device__ __half g_w2[(size_t)NE * HD * ID];
__device__ __half g_act[(size_t)NE * NT * ID];

// ---------------- helpers ----------------
__device__ __forceinline__ void cp16(uint32_t dst, const void* src) {
    asm volatile("cp.async.cg.shared.global [%0], [%1], 16;" :: "r"(dst), "l"(src));
}
#define CP_COMMIT() asm volatile("cp.async.commit_group;" ::: "memory")
template <int N>
__device__ __forceinline__ void cp_wait() {
    asm volatile("cp.async.wait_group %0;" :: "n"(N) : "memory");
}
__device__ __forceinline__ uint32_t smem_to_u32(const void* p) {
    uint32_t a;
    asm("{ .reg .u64 t; cvta.to.shared.u64 t, %1; cvt.u32.u64 %0, t; }" : "=r"(a) : "l"(p));
    return a;
}
__device__ __forceinline__ void ldsm_x4(uint32_t* r, uint32_t addr) {
    asm volatile("ldmatrix.sync.aligned.m8n8.x4.shared.b16 {%0,%1,%2,%3}, [%4];"
                 : "=r"(r[0]), "=r"(r[1]), "=r"(r[2]), "=r"(r[3]) : "r"(addr));
}
__device__ __forceinline__ void mma16816(float* d, const uint32_t* a, const uint32_t* b) {
    asm volatile(
        "mma.sync.aligned.m16n8k16.row.col.f32.f16.f16.f32 "
        "{%0,%1,%2,%3}, {%4,%5,%6,%7}, {%8,%9}, {%0,%1,%2,%3};"
        : "+f"(d[0]), "+f"(d[1]), "+f"(d[2]), "+f"(d[3])
        : "r"(a[0]), "r"(a[1]), "r"(a[2]), "r"(a[3]), "r"(b[0]), "r"(b[1]));
}
__device__ __forceinline__ float gelu_exact(float v) {
    return 0.5f * v * (1.f + erff(v * 0.70710678118654752f));
}

// ---------------- zero the output (for atomic combine) ----------------
__global__ void zero_kernel(float4* __restrict__ p, int n4) {
    int i = blockIdx.x * blockDim.x + threadIdx.x;
    int stride = gridDim.x * blockDim.x;
    for (; i < n4; i += stride) p[i] = make_float4(0.f, 0.f, 0.f, 0.f);
}

// ---------------- router + x->fp16 conversion fused: one warp per token ----------------
__global__ void router_kernel(const float* __restrict__ x,
                              const float* __restrict__ Wg) {
    int warp = (blockIdx.x * blockDim.x + threadIdx.x) >> 5;
    int lane = threadIdx.x & 31;
    if (warp >= NT) return;
    const float4* xr = (const float4*)(x + (size_t)warp * HD);

    float4 xv[8];
#pragma unroll
    for (int j = 0; j < 8; j++) xv[j] = xr[lane + j * 32];

    __half2* xo = (__half2*)(g_xh + (size_t)warp * HD);
#pragma unroll
    for (int j = 0; j < 8; j++) {
        int c2 = (lane + j * 32) * 2;
        xo[c2 + 0] = __half2(__float2half_rn(xv[j].x), __float2half_rn(xv[j].y));
        xo[c2 + 1] = __half2(__float2half_rn(xv[j].z), __float2half_rn(xv[j].w));
    }

    float logit[NE];
#pragma unroll
    for (int e = 0; e < NE; e++) {
        const float4* w = (const float4*)(Wg + e * HD);
        float s = 0.f;
#pragma unroll
        for (int j = 0; j < 8; j++) {
            float4 wv = w[lane + j * 32];
            s += xv[j].x * wv.x + xv[j].y * wv.y + xv[j].z * wv.z + xv[j].w * wv.w;
        }
#pragma unroll
        for (int o = 16; o; o >>= 1) s += __shfl_xor_sync(0xffffffffu, s, o);
        logit[e] = s;
    }

    if (lane == 0) {
        int e0 = 0; float l0 = logit[0];
#pragma unroll
        for (int e = 1; e < NE; e++) if (logit[e] > l0) { l0 = logit[e]; e0 = e; }
        int e1 = -1; float l1 = -3.0e38f;
#pragma unroll
        for (int e = 0; e < NE; e++)
            if (e != e0 && logit[e] > l1) { l1 = logit[e]; e1 = e; }
        float w0 = 1.f / (1.f + expf(l1 - l0));
        float w1 = 1.f - w0;

        int s0 = atomicAdd(&g_cnt[e0], 1);
        g_tok[e0 * NT + s0] = warp;
        g_wgt[e0 * NT + s0] = w0;

        int s1 = atomicAdd(&g_cnt[e1], 1);
        g_tok[e1 * NT + s1] = warp;
        g_wgt[e1 * NT + s1] = w1;
    }
}

// ---------------- f32 -> fp16 conversion (weights), 16B stores ----------------
__global__ void wconv_kernel(const float4* __restrict__ src,
                             uint4* __restrict__ h, int n8) {
    int i = blockIdx.x * blockDim.x + threadIdx.x;
    int stride = gridDim.x * blockDim.x;
    for (; i < n8; i += stride) {
        float4 v0 = src[2 * i + 0];
        float4 v1 = src[2 * i + 1];
        __half2 a(__float2half_rn(v0.x), __float2half_rn(v0.y));
        __half2 b(__float2half_rn(v0.z), __float2half_rn(v0.w));
        __half2 c(__float2half_rn(v1.x), __float2half_rn(v1.y));
        __half2 d(__float2half_rn(v1.z), __float2half_rn(v1.w));
        uint4 o;
        o.x = *(uint32_t*)&a; o.y = *(uint32_t*)&b;
        o.z = *(uint32_t*)&c; o.w = *(uint32_t*)&d;
        h[i] = o;
    }
}

// ---------------- GEMM tile body (shared by both layers) ----------------
template <int KDIM, int BROWS, bool GELU_OUT, bool GATHER_A, int TBM, int TBN, int WTM, int WTN>
__device__ __forceinline__ void ffn_body(int m0, int n0, int e, int cnt,
                                         const __half* __restrict__ A,
                                         const __half* __restrict__ B,
                                         const float* __restrict__ bias,
                                         float* __restrict__ out, char* smem) {
    constexpr int STAGE = (TBM + TBN) * ROWB;
    constexpr int MT = WTM / 16;
    constexpr int PT = WTN / 16;
    constexpr int NS = KDIM / BK;
    constexpr int AJ = TBM * 8 / 256;
    constexpr int BJ = TBN * 8 / 256;

    uint32_t sb = smem_to_u32(smem);
    int tid = threadIdx.x;
    int wid = tid >> 5;
    int lane = tid & 31;
    int g = lane >> 2, t = lane & 3;
    int wm = (wid >> 2) * WTM;
    int wn = (wid & 3) * WTN;

    int la = lane & 7;
    int ar = la + 8 * ((lane >> 3) & 1);
    int ak = 8 * (lane >> 4);
    int br = la + 8 * ((lane >> 4) & 1);
    int bk = 8 * ((lane >> 3) & 1);

    const __half* aptr[AJ]; uint32_t aoff[AJ];
    const __half* bptr[BJ]; uint32_t boff[BJ];
#pragma unroll
    for (int j = 0; j < AJ; j++) {
        int c = tid + j * 256;
        int r = c >> 3, ch = c & 7;
        aoff[j] = (uint32_t)(r * ROWB + ch * 16);
        int m = m0 + r;
        if (GATHER_A) {
            int mm = (m < cnt) ? m : (cnt - 1);
            aptr[j] = A + (size_t)g_tok[e * NT + mm] * KDIM + ch * 8;
        } else {
            aptr[j] = A + (size_t)(e * NT + m) * KDIM + ch * 8;
        }
    }
#pragma unroll
    for (int j = 0; j < BJ; j++) {
        int c = tid + j * 256;
        int r = c >> 3, ch = c & 7;
        boff[j] = (uint32_t)(TBM * ROWB + r * ROWB + ch * 16);
        bptr[j] = B + (size_t)(e * BROWS + n0 + r) * KDIM + ch * 8;
    }

    auto load_stage = [&](uint32_t base, int k0) {
#pragma unroll
        for (int j = 0; j < AJ; j++) cp16(base + aoff[j], aptr[j] + k0);
#pragma unroll
        for (int j = 0; j < BJ; j++) cp16(base + boff[j], bptr[j] + k0);
    };

    load_stage(sb, 0);
    CP_COMMIT();

    float acc[MT][WTN / 8][4] = {};

    for (int i = 0; i < NS; i++) {
        if (i + 1 < NS) {
            load_stage(sb + (uint32_t)(((i + 1) & 1) * STAGE), (i + 1) * BK);
            CP_COMMIT();
        }
        if (i + 1 < NS) cp_wait<1>(); else cp_wait<0>();
        __syncthreads();

        uint32_t sAu = sb + (uint32_t)((i & 1) * STAGE);
        uint32_t sBu = sAu + TBM * ROWB;

#pragma unroll
        for (int kk = 0; kk < BK; kk += 16) {
            uint32_t AH[MT][4], BB[PT][4];
#pragma unroll
            for (int mt = 0; mt < MT; mt++)
                ldsm_x4(AH[mt], sAu + (uint32_t)(((wm + mt * 16 + ar) * SA + kk + ak) * 2));
#pragma unroll
            for (int p = 0; p < PT; p++)
                ldsm_x4(BB[p], sBu + (uint32_t)(((wn + p * 16 + br) * SA + kk + bk) * 2));
#pragma unroll
            for (int p = 0; p < PT; p++) {
#pragma unroll
                for (int mt = 0; mt < MT; mt++) {
                    mma16816(acc[mt][2 * p + 0], AH[mt], &BB[p][0]);
                    mma16816(acc[mt][2 * p + 1], AH[mt], &BB[p][2]);
                }
            }
        }
        __syncthreads();
    }

#pragma unroll
    for (int mt = 0; mt < MT; mt++) {
        int r0 = m0 + wm + mt * 16 + g;
        int r1 = r0 + 8;
        int tok0 = 0, tok1 = 0;
        float wg0 = 0.f, wg1 = 0.f;
        bool ok0 = false, ok1 = false;
        if (!GELU_OUT) {
            ok0 = (r0 < cnt);
            ok1 = (r1 < cnt);
            if (ok0) { tok0 = g_tok[e * NT + r0]; wg0 = g_wgt[e * NT + r0]; }
            if (ok1) { tok1 = g_tok[e * NT + r1]; wg1 = g_wgt[e * NT + r1]; }
        }
#pragma unroll
        for (int nt = 0; nt < WTN / 8; nt++) {
            int col = n0 + wn + nt * 8 + 2 * t;
            float2 bb = *(const float2*)&bias[(size_t)e * BROWS + col];
            float* c = acc[mt][nt];
            float v00 = c[0] + bb.x, v01 = c[1] + bb.y;
            float v10 = c[2] + bb.x, v11 = c[3] + bb.y;
            if (GELU_OUT) {
                float g00 = gelu_exact(v00), g01 = gelu_exact(v01);
                float g10 = gelu_exact(v10), g11 = gelu_exact(v11);
                size_t o0 = ((size_t)e * NT + r0) * ID + col;
                size_t o1 = ((size_t)e * NT + r1) * ID + col;
                *(__half2*)&g_act[o0] = __half2(__float2half_rn(g00), __float2half_rn(g01));
                *(__half2*)&g_act[o1] = __half2(__float2half_rn(g10), __float2half_rn(g11));
            } else {
                if (ok0) {
                    atomicAdd(&out[(size_t)tok0 * HD + col + 0], wg0 * v00);
                    atomicAdd(&out[(size_t)tok0 * HD + col + 1], wg0 * v01);
                }
                if (ok1) {
                    atomicAdd(&out[(size_t)tok1 * HD + col + 0], wg1 * v10);
                    atomicAdd(&out[(size_t)tok1 * HD + col + 1], wg1 * v11);
                }
            }
        }
    }
}

// ---------------- FFN1: persistent work queue over compacted active tiles ----------------
// per expert: mb_e = ceil(cnt_e/128) m-blocks x 16 n-blocks; m fastest (B L2 reuse)
__global__ void __launch_bounds__(256)
ffn1_kernel(const __half* __restrict__ xh, const __half* __restrict__ w1,
            const float* __restrict__ b1) {
    extern __shared__ char smem[];
    __shared__ int sTile;
    int tid = threadIdx.x;

    int cnt[NE], mb[NE];
#pragma unroll
    for (int e = 0; e < NE; e++) {
        cnt[e] = g_cnt[e];
        mb[e] = (cnt[e] + 127) >> 7;
    }

    for (;;) {
        if (tid == 0) sTile = atomicAdd(&g_work1, 1);
        __syncthreads();
        int t = sTile;

        int e = 0;
#pragma unroll
        for (int i = 0; i < NE; i++) {
            int sz = mb[i] * 16;
            if (t >= sz && e == i) { t -= sz; e = i + 1; }
        }
        if (e >= NE) break;

        int m0 = (t % mb[e]) * 128;
        int n0 = (t / mb[e]) * 256;
        ffn_body<HD, ID, true, true, 128, 256, 64, 64>(
            m0, n0, e, cnt[e], xh, w1, b1, nullptr, smem);
        __syncthreads();   // epilogue done before next claim overwrites sTile/smem
    }
}

// ---------------- FFN2: persistent work queue + fused combine + state reset ----------------
// per expert: mb_e = ceil(cnt_e/64) m-blocks x 8 n-blocks; m fastest
__global__ void __launch_bounds__(256)
ffn2_kernel(const __half* __restrict__ w2, const float* __restrict__ b2,
            float* __restrict__ out) {
    extern __shared__ char smem[];
    __shared__ int sTile;
    int tid = threadIdx.x;

    int cnt[NE], mb[NE];
#pragma unroll
    for (int e = 0; e < NE; e++) {
        cnt[e] = g_cnt[e];
        mb[e] = (cnt[e] + 63) >> 6;
    }

    for (;;) {
        if (tid == 0) sTile = atomicAdd(&g_work2, 1);
        __syncthreads();
        int t = sTile;

        int e = 0;
#pragma unroll
        for (int i = 0; i < NE; i++) {
            int sz = mb[i] * 8;
            if (t >= sz && e == i) { t -= sz; e = i + 1; }
        }
        if (e >= NE) break;

        int m0 = (t % mb[e]) * 64;
        int n0 = (t / mb[e]) * 128;
        ffn_body<ID, HD, false, false, 64, 128, 32, 32>(
            m0, n0, e, cnt[e], g_act, w2, b2, out, smem);
        __syncthreads();
    }

    // last CTA to exit resets all device state for the next (replayed) call
    if (tid == 0) {
        __threadfence();
        if (atomicAdd(&g_exit, 1) == (int)gridDim.x - 1) {
#pragma unroll
            for (int i = 0; i < NE; i++) g_cnt[i] = 0;
            g_work1 = 0;
            g_work2 = 0;
            g_exit = 0;
            __threadfence();
        }
    }
}

#define FFN1_SMEM (2 * (128 + 256) * ROWB)
#define FFN2_SMEM (2 * (64 + 128) * ROWB)

extern "C" void kernel_launch(void* const* d_in, const int* in_sizes, int n_in,
                              void* d_out, int out_size) {
    const float* x  = (const float*)d_in[0];
    const float* Wg = (const float*)d_in[1];
    const float* W1 = (const float*)d_in[2];
    const float* b1 = (const float*)d_in[3];
    const float* W2 = (const float*)d_in[4];
    const float* b2 = (const float*)d_in[5];
    float* out = (float*)d_out;

    static int init_done = 0;
    static int n_sms = 0;
    static cudaStream_t sW;
    static cudaEvent_t evFork, evW1, evW2;
    if (!init_done) {
        cudaFuncSetAttribute((const void*)ffn1_kernel,
                             cudaFuncAttributeMaxDynamicSharedMemorySize, FFN1_SMEM);
        cudaFuncSetAttribute((const void*)ffn2_kernel,
                             cudaFuncAttributeMaxDynamicSharedMemorySize, FFN2_SMEM);
        cudaDeviceGetAttribute(&n_sms, cudaDevAttrMultiProcessorCount, 0);
        cudaStreamCreateWithFlags(&sW, cudaStreamNonBlocking);
        cudaEventCreateWithFlags(&evFork, cudaEventDisableTiming);
        cudaEventCreateWithFlags(&evW1, cudaEventDisableTiming);
        cudaEventCreateWithFlags(&evW2, cudaEventDisableTiming);
        init_done = 1;
    }

    uint4 *w1, *w2;
    cudaGetSymbolAddress((void**)&w1, g_w1);
    cudaGetSymbolAddress((void**)&w2, g_w2);
    const __half* xhp;
    cudaGetSymbolAddress((void**)&xhp, g_xh);

    const int n8w = NE * ID * HD / 8;

    // fork: side stream converts W1 (gates FFN1), zeroes out, converts W2 (gates FFN2);
    // main stream routes (+x conversion) in parallel
    cudaEventRecord(evFork, 0);
    cudaStreamWaitEvent(sW, evFork, 0);
    wconv_kernel<<<4096, 256, 0, sW>>>((const float4*)W1, w1, n8w);
    cudaEventRecord(evW1, sW);
    zero_kernel<<<1024, 256, 0, sW>>>((float4*)out, NT * HD / 4);
    wconv_kernel<<<4096, 256, 0, sW>>>((const float4*)W2, w2, n8w);
    cudaEventRecord(evW2, sW);

    router_kernel<<<NT / 8, 256>>>(x, Wg);

    cudaStreamWaitEvent(0, evW1, 0);
    ffn1_kernel<<<n_sms, 256, FFN1_SMEM>>>(xhp, (const __half*)w1, b1);

    cudaStreamWaitEvent(0, evW2, 0);   // FFN2 needs w2 + zeroed out
    ffn2_kernel<<<2 * n_sms, 256, FFN2_SMEM>>>((const __half*)w2, b2, out);
}

// round 16
// speedup vs baseline: 1.2808x; 1.0661x over previous
#include <cuda_runtime.h>
#include <cuda_fp16.h>
#include <math.h>
#include <stdint.h>

#define NT 4096   // tokens (B*S)
#define HD 1024   // hidden
#define ID 4096   // intermediate
#define NE 8      // experts

#define BK 64
#define SA 72                 // SMEM row stride (fp16 elems): 64 data + 8 pad (144B)
#define ROWB 144

// ---------------- scratch (static device globals; no allocs) ----------------
__device__ int   g_cnt[NE];
__device__ int   g_done;
__device__ int   g_tok[NE * NT];
__device__ float g_wgt[NE * NT];
__device__ __half g_xh[(size_t)NT * HD];
__device__ __half g_w1[(size_t)NE * ID * HD];
__device__ __half g_w2[(size_t)NE * HD * ID];
__device__ __half g_act[(size_t)NE * NT * ID];

// ---------------- helpers ----------------
__device__ __forceinline__ void cp16(uint32_t dst, const void* src) {
    asm volatile("cp.async.cg.shared.global [%0], [%1], 16;" :: "r"(dst), "l"(src));
}
#define CP_COMMIT() asm volatile("cp.async.commit_group;" ::: "memory")
template <int N>
__device__ __forceinline__ void cp_wait() {
    asm volatile("cp.async.wait_group %0;" :: "n"(N) : "memory");
}
__device__ __forceinline__ uint32_t smem_to_u32(const void* p) {
    uint32_t a;
    asm("{ .reg .u64 t; cvta.to.shared.u64 t, %1; cvt.u32.u64 %0, t; }" : "=r"(a) : "l"(p));
    return a;
}
__device__ __forceinline__ void ldsm_x4(uint32_t* r, uint32_t addr) {
    asm volatile("ldmatrix.sync.aligned.m8n8.x4.shared.b16 {%0,%1,%2,%3}, [%4];"
                 : "=r"(r[0]), "=r"(r[1]), "=r"(r[2]), "=r"(r[3]) : "r"(addr));
}
__device__ __forceinline__ void mma16816(float* d, const uint32_t* a, const uint32_t* b) {
    asm volatile(
        "mma.sync.aligned.m16n8k16.row.col.f32.f16.f16.f32 "
        "{%0,%1,%2,%3}, {%4,%5,%6,%7}, {%8,%9}, {%0,%1,%2,%3};"
        : "+f"(d[0]), "+f"(d[1]), "+f"(d[2]), "+f"(d[3])
        : "r"(a[0]), "r"(a[1]), "r"(a[2]), "r"(a[3]), "r"(b[0]), "r"(b[1]));
}
__device__ __forceinline__ float gelu_exact(float v) {
    return 0.5f * v * (1.f + erff(v * 0.70710678118654752f));
}

// ---------------- zero the output (for atomic combine) ----------------
__global__ void zero_kernel(float4* __restrict__ p, int n4) {
    int i = blockIdx.x * blockDim.x + threadIdx.x;
    int stride = gridDim.x * blockDim.x;
    for (; i < n4; i += stride) p[i] = make_float4(0.f, 0.f, 0.f, 0.f);
}

// ---------------- router + x->fp16 conversion fused: one warp per token ----------------
__global__ void router_kernel(const float* __restrict__ x,
                              const float* __restrict__ Wg) {
    int warp = (blockIdx.x * blockDim.x + threadIdx.x) >> 5;
    int lane = threadIdx.x & 31;
    if (warp >= NT) return;
    const float4* xr = (const float4*)(x + (size_t)warp * HD);

    float4 xv[8];
#pragma unroll
    for (int j = 0; j < 8; j++) xv[j] = xr[lane + j * 32];

    __half2* xo = (__half2*)(g_xh + (size_t)warp * HD);
#pragma unroll
    for (int j = 0; j < 8; j++) {
        int c2 = (lane + j * 32) * 2;
        xo[c2 + 0] = __half2(__float2half_rn(xv[j].x), __float2half_rn(xv[j].y));
        xo[c2 + 1] = __half2(__float2half_rn(xv[j].z), __float2half_rn(xv[j].w));
    }

    float logit[NE];
#pragma unroll
    for (int e = 0; e < NE; e++) {
        const float4* w = (const float4*)(Wg + e * HD);
        float s = 0.f;
#pragma unroll
        for (int j = 0; j < 8; j++) {
            float4 wv = w[lane + j * 32];
            s += xv[j].x * wv.x + xv[j].y * wv.y + xv[j].z * wv.z + xv[j].w * wv.w;
        }
#pragma unroll
        for (int o = 16; o; o >>= 1) s += __shfl_xor_sync(0xffffffffu, s, o);
        logit[e] = s;
    }

    if (lane == 0) {
        int e0 = 0; float l0 = logit[0];
#pragma unroll
        for (int e = 1; e < NE; e++) if (logit[e] > l0) { l0 = logit[e]; e0 = e; }
        int e1 = -1; float l1 = -3.0e38f;
#pragma unroll
        for (int e = 0; e < NE; e++)
            if (e != e0 && logit[e] > l1) { l1 = logit[e]; e1 = e; }
        float w0 = 1.f / (1.f + expf(l1 - l0));
        float w1 = 1.f - w0;

        int s0 = atomicAdd(&g_cnt[e0], 1);
        g_tok[e0 * NT + s0] = warp;
        g_wgt[e0 * NT + s0] = w0;

        int s1 = atomicAdd(&g_cnt[e1], 1);
        g_tok[e1 * NT + s1] = warp;
        g_wgt[e1 * NT + s1] = w1;
    }
}

// ---------------- f32 -> fp16 conversion (weights), 16B stores ----------------
__global__ void wconv_kernel(const float4* __restrict__ src,
                             uint4* __restrict__ h, int n8) {
    int i = blockIdx.x * blockDim.x + threadIdx.x;
    int stride = gridDim.x * blockDim.x;
    for (; i < n8; i += stride) {
        float4 v0 = src[2 * i + 0];
        float4 v1 = src[2 * i + 1];
        __half2 a(__float2half_rn(v0.x), __float2half_rn(v0.y));
        __half2 b(__float2half_rn(v0.z), __float2half_rn(v0.w));
        __half2 c(__float2half_rn(v1.x), __float2half_rn(v1.y));
        __half2 d(__float2half_rn(v1.z), __float2half_rn(v1.w));
        uint4 o;
        o.x = *(uint32_t*)&a; o.y = *(uint32_t*)&b;
        o.z = *(uint32_t*)&c; o.w = *(uint32_t*)&d;
        h[i] = o;
    }
}

// ---------------- single-pass fp16 HMMA GEMM, BK=64 double-buffered ----------------
// GELU_OUT=true : FFN1, A gathered by token index; writes gelu(acc+bias) to g_act
// GELU_OUT=false: FFN2, dense A; fused combine: atomicAdd(out[tok], w*(acc+bias));
//                 last CTA resets g_cnt for the next call.
template <int KDIM, int BROWS, bool GELU_OUT, bool GATHER_A, int TBM, int TBN, int WTM, int WTN>
__global__ void __launch_bounds__(256, 2)
moe_mma_kernel(const __half* __restrict__ A, const __half* __restrict__ B,
               const float* __restrict__ bias, float* __restrict__ out) {
    constexpr int STAGE = (TBM + TBN) * ROWB;
    constexpr int MT = WTM / 16;
    constexpr int PT = WTN / 16;
    constexpr int NS = KDIM / BK;
    constexpr int AJ = TBM * 8 / 256;
    constexpr int BJ = TBN * 8 / 256;

    int e = blockIdx.z;
    int cnt = g_cnt[e];
    int m0 = blockIdx.x * TBM;
    bool active = (m0 < cnt);
    if (GELU_OUT && !active) return;

    extern __shared__ char smem[];

    if (active) {
        uint32_t sb = smem_to_u32(smem);
        int n0 = blockIdx.y * TBN;
        int tid = threadIdx.x;
        int wid = tid >> 5;
        int lane = tid & 31;
        int g = lane >> 2, t = lane & 3;
        int wm = (wid >> 2) * WTM;
        int wn = (wid & 3) * WTN;

        int la = lane & 7;
        int ar = la + 8 * ((lane >> 3) & 1);
        int ak = 8 * (lane >> 4);
        int br = la + 8 * ((lane >> 4) & 1);
        int bk = 8 * ((lane >> 3) & 1);

        const __half* aptr[AJ]; uint32_t aoff[AJ];
        const __half* bptr[BJ]; uint32_t boff[BJ];
#pragma unroll
        for (int j = 0; j < AJ; j++) {
            int c = tid + j * 256;
            int r = c >> 3, ch = c & 7;
            aoff[j] = (uint32_t)(r * ROWB + ch * 16);
            int m = m0 + r;
            if (GATHER_A) {
                int mm = (m < cnt) ? m : (cnt - 1);
                aptr[j] = A + (size_t)g_tok[e * NT + mm] * KDIM + ch * 8;
            } else {
                aptr[j] = A + (size_t)(e * NT + m) * KDIM + ch * 8;
            }
        }
#pragma unroll
        for (int j = 0; j < BJ; j++) {
            int c = tid + j * 256;
            int r = c >> 3, ch = c & 7;
            boff[j] = (uint32_t)(TBM * ROWB + r * ROWB + ch * 16);
            bptr[j] = B + (size_t)(e * BROWS + n0 + r) * KDIM + ch * 8;
        }

        auto load_stage = [&](uint32_t base, int k0) {
#pragma unroll
            for (int j = 0; j < AJ; j++) cp16(base + aoff[j], aptr[j] + k0);
#pragma unroll
            for (int j = 0; j < BJ; j++) cp16(base + boff[j], bptr[j] + k0);
        };

        load_stage(sb, 0);
        CP_COMMIT();

        float acc[MT][WTN / 8][4] = {};

        for (int i = 0; i < NS; i++) {
            if (i + 1 < NS) {
                load_stage(sb + (uint32_t)(((i + 1) & 1) * STAGE), (i + 1) * BK);
                CP_COMMIT();
            }
            if (i + 1 < NS) cp_wait<1>(); else cp_wait<0>();
            __syncthreads();

            uint32_t sAu = sb + (uint32_t)((i & 1) * STAGE);
            uint32_t sBu = sAu + TBM * ROWB;

#pragma unroll
            for (int kk = 0; kk < BK; kk += 16) {
                uint32_t AH[MT][4], BB[PT][4];
#pragma unroll
                for (int mt = 0; mt < MT; mt++)
                    ldsm_x4(AH[mt], sAu + (uint32_t)(((wm + mt * 16 + ar) * SA + kk + ak) * 2));
#pragma unroll
                for (int p = 0; p < PT; p++)
                    ldsm_x4(BB[p], sBu + (uint32_t)(((wn + p * 16 + br) * SA + kk + bk) * 2));
#pragma unroll
                for (int p = 0; p < PT; p++) {
#pragma unroll
                    for (int mt = 0; mt < MT; mt++) {
                        mma16816(acc[mt][2 * p + 0], AH[mt], &BB[p][0]);
                        mma16816(acc[mt][2 * p + 1], AH[mt], &BB[p][2]);
                    }
                }
            }
            __syncthreads();
        }

        // ---------------- epilogue ----------------
#pragma unroll
        for (int mt = 0; mt < MT; mt++) {
            int r0 = m0 + wm + mt * 16 + g;
            int r1 = r0 + 8;
            int tok0 = 0, tok1 = 0;
            float wg0 = 0.f, wg1 = 0.f;
            bool ok0 = false, ok1 = false;
            if (!GELU_OUT) {
                ok0 = (r0 < cnt);
                ok1 = (r1 < cnt);
                if (ok0) { tok0 = g_tok[e * NT + r0]; wg0 = g_wgt[e * NT + r0]; }
                if (ok1) { tok1 = g_tok[e * NT + r1]; wg1 = g_wgt[e * NT + r1]; }
            }
#pragma unroll
            for (int nt = 0; nt < WTN / 8; nt++) {
                int col = n0 + wn + nt * 8 + 2 * t;
                float2 bb = *(const float2*)&bias[(size_t)e * BROWS + col];
                float* c = acc[mt][nt];
                float v00 = c[0] + bb.x, v01 = c[1] + bb.y;
                float v10 = c[2] + bb.x, v11 = c[3] + bb.y;
                if (GELU_OUT) {
                    float g00 = gelu_exact(v00), g01 = gelu_exact(v01);
                    float g10 = gelu_exact(v10), g11 = gelu_exact(v11);
                    size_t o0 = ((size_t)e * NT + r0) * ID + col;
                    size_t o1 = ((size_t)e * NT + r1) * ID + col;
                    *(__half2*)&g_act[o0] = __half2(__float2half_rn(g00), __float2half_rn(g01));
                    *(__half2*)&g_act[o1] = __half2(__float2half_rn(g10), __float2half_rn(g11));
                } else {
                    if (ok0) {
                        atomicAdd(&out[(size_t)tok0 * HD + col + 0], wg0 * v00);
                        atomicAdd(&out[(size_t)tok0 * HD + col + 1], wg0 * v01);
                    }
                    if (ok1) {
                        atomicAdd(&out[(size_t)tok1 * HD + col + 0], wg1 * v10);
                        atomicAdd(&out[(size_t)tok1 * HD + col + 1], wg1 * v11);
                    }
                }
            }
        }
    }

    // ---------------- FFN2 only: last CTA resets routing state for next call ----------------
    if (!GELU_OUT) {
        __syncthreads();
        if (threadIdx.x == 0) {
            __threadfence();
            int total = (int)(gridDim.x * gridDim.y * gridDim.z);
            if (atomicAdd(&g_done, 1) == total - 1) {
#pragma unroll
                for (int i = 0; i < NE; i++) g_cnt[i] = 0;
                g_done = 0;
                __threadfence();
            }
        }
    }
}

// FFN1: 128x128 block, 64x32 warp tile (72KB smem -> 2 CTAs/SM).
// FFN2: 64x128 block, 32x32 warp tile (55KB smem -> 2 CTAs/SM).
#define FFN1_SMEM (2 * (128 + 128) * ROWB)
#define FFN2_SMEM (2 * (64 + 128) * ROWB)

extern "C" void kernel_launch(void* const* d_in, const int* in_sizes, int n_in,
                              void* d_out, int out_size) {
    const float* x  = (const float*)d_in[0];
    const float* Wg = (const float*)d_in[1];
    const float* W1 = (const float*)d_in[2];
    const float* b1 = (const float*)d_in[3];
    const float* W2 = (const float*)d_in[4];
    const float* b2 = (const float*)d_in[5];
    float* out = (float*)d_out;

    static int init_done = 0;
    static cudaStream_t sW;
    static cudaEvent_t evFork, evW1, evW2;
    if (!init_done) {
        cudaFuncSetAttribute(
            (const void*)moe_mma_kernel<HD, ID, true, true, 128, 128, 64, 32>,
            cudaFuncAttributeMaxDynamicSharedMemorySize, FFN1_SMEM);
        cudaFuncSetAttribute(
            (const void*)moe_mma_kernel<ID, HD, false, false, 64, 128, 32, 32>,
            cudaFuncAttributeMaxDynamicSharedMemorySize, FFN2_SMEM);
        cudaStreamCreateWithFlags(&sW, cudaStreamNonBlocking);
        cudaEventCreateWithFlags(&evFork, cudaEventDisableTiming);
        cudaEventCreateWithFlags(&evW1, cudaEventDisableTiming);
        cudaEventCreateWithFlags(&evW2, cudaEventDisableTiming);
        init_done = 1;
    }

    uint4 *w1, *w2;
    cudaGetSymbolAddress((void**)&w1, g_w1);
    cudaGetSymbolAddress((void**)&w2, g_w2);
    const __half *xhp, *actp;
    cudaGetSymbolAddress((void**)&xhp, g_xh);
    cudaGetSymbolAddress((void**)&actp, g_act);

    const int n8w = NE * ID * HD / 8;

    // fork: side stream converts W1 (gates FFN1), zeroes out, converts W2 (gates FFN2);
    // main stream routes (+x conversion) in parallel
    cudaEventRecord(evFork, 0);
    cudaStreamWaitEvent(sW, evFork, 0);
    wconv_kernel<<<4096, 256, 0, sW>>>((const float4*)W1, w1, n8w);
    cudaEventRecord(evW1, sW);
    zero_kernel<<<1024, 256, 0, sW>>>((float4*)out, NT * HD / 4);
    wconv_kernel<<<4096, 256, 0, sW>>>((const float4*)W2, w2, n8w);
    cudaEventRecord(evW2, sW);

    router_kernel<<<NT / 8, 256>>>(x, Wg);

    cudaStreamWaitEvent(0, evW1, 0);   // FFN1 needs w1 (zero+wconv2 hide under FFN1)
    moe_mma_kernel<HD, ID, true, true, 128, 128, 64, 32>
        <<<dim3(NT / 128, ID / 128, NE), 256, FFN1_SMEM>>>(
            xhp, (const __half*)w1, b1, nullptr);

    cudaStreamWaitEvent(0, evW2, 0);   // FFN2 needs w2 + zeroed out
    moe_mma_kernel<ID, HD, false, false, 64, 128, 32, 32>
        <<<dim3(NT / 64, HD / 128, NE), 256, FFN2_SMEM>>>(
            actp, (const __half*)w2, b2, out);
}